// round 3
// baseline (speedup 1.0000x reference)
#include <cuda_runtime.h>
#include <cuda_bf16.h>

// TemplateEncoder: output (B=2, N=1024, N=1024, 16) fp32.
//
// Key observation: one_hot(bin,22) @ W + b -> LayerNorm -> ReLU depends ONLY on
// the bin index (22 possible values). Precompute relu(LN(W[k]+b)*gamma+beta)
// as a 22x16 table; each output row is table[bin] * min(conf_i, conf_j).
// The kernel is then pure store-bandwidth: 128 MiB of coalesced float4 stores.

namespace {

constexpr int   TD      = 16;
constexpr float BIN_W   = 40.0f / 21.0f;   // bin_width = MAX_DIST / (NUM_BINS-1)
constexpr float INV_W   = 21.0f / 40.0f;
constexpr int   TBL_STRIDE = 20;           // padded row stride (floats): 80B, 16B-aligned, bank-spread

__global__ __launch_bounds__(256, 8) void template_encoder_kernel(
    const float* __restrict__ coords,   // (B, N, 3)
    const float* __restrict__ conf,     // (B, N)
    const float* __restrict__ Wm,       // (22, 16)
    const float* __restrict__ bv,       // (16)
    const float* __restrict__ gam,      // (16)
    const float* __restrict__ bet,      // (16)
    float4* __restrict__ out)           // (B*N*N*16 floats) viewed as float4
{
    __shared__ float table[22][TBL_STRIDE];
    __shared__ float s_cj[3][64];
    __shared__ float s_cfj[64];

    const int tid = threadIdx.x;

    // ---- build the 22x16 bin table: relu(LN(W[k] + b) * gamma + beta) ----
    if (tid < 22) {
        float h[TD];
        float mu = 0.0f;
        #pragma unroll
        for (int d = 0; d < TD; ++d) {
            h[d] = Wm[tid * TD + d] + bv[d];
            mu += h[d];
        }
        mu *= (1.0f / TD);
        float var = 0.0f;
        #pragma unroll
        for (int d = 0; d < TD; ++d) {
            float t = h[d] - mu;
            var = fmaf(t, t, var);
        }
        var *= (1.0f / TD);
        float inv = rsqrtf(var + 1e-5f);
        #pragma unroll
        for (int d = 0; d < TD; ++d) {
            float v = (h[d] - mu) * inv * gam[d] + bet[d];
            table[tid][d] = fmaxf(v, 0.0f);
        }
    }

    // ---- block = 64 consecutive rows (same batch b, same i, j0..j0+63) ----
    const int r0   = blockIdx.x << 6;       // first (b,i,j) row of this block
    const int bidx = r0 >> 20;              // N*N = 2^20 rows per batch
    const int i    = (r0 >> 10) & 1023;
    const int j0   = r0 & 1023;             // multiple of 64

    if (tid < 64) {
        int gj = (bidx << 10) + j0 + tid;
        s_cj[0][tid] = coords[gj * 3 + 0];
        s_cj[1][tid] = coords[gj * 3 + 1];
        s_cj[2][tid] = coords[gj * 3 + 2];
        s_cfj[tid]   = conf[gj];
    }
    __syncthreads();

    const int gi = (bidx << 10) + i;
    const float cix = __ldg(coords + gi * 3 + 0);   // broadcast across block
    const float ciy = __ldg(coords + gi * 3 + 1);
    const float ciz = __ldg(coords + gi * 3 + 2);
    const float cfi = __ldg(conf + gi);

    const int jl   = tid >> 2;   // local row (j) index: 4 threads per row
    const int part = tid & 3;    // which float4 of the 16-float row

    const float dx = cix - s_cj[0][jl];
    const float dy = ciy - s_cj[1][jl];
    const float dz = ciz - s_cj[2][jl];
    const float dist = sqrtf(fmaf(dx, dx, fmaf(dy, dy, fmaf(dz, dz, 1e-8f))));

    // searchsorted(edges, dist, side='left') == #{m in [0,20] : m*BIN_W < dist},
    // then clipped to [0, 20]. Initial guess via division, exact +/-1 refine
    // against the same f32 edge values (m * BIN_W) the reference uses.
    int c = (int)(dist * INV_W);
    if (c > 21) c = 21;
    int cnt = c + 1;
    if (c <= 20 && (float)c * BIN_W >= dist)            cnt = c;
    else if (c + 1 <= 20 && (float)(c + 1) * BIN_W < dist) cnt = c + 2;
    int bin = cnt > 20 ? 20 : cnt;

    const float cfj = s_cfj[jl];
    if (!(cfi > 0.0f) || !(cfj > 0.0f)) bin = 21;       // no_template_bin
    const float cp = fminf(cfi, cfj);

    float4 v = *reinterpret_cast<const float4*>(&table[bin][part << 2]);
    v.x *= cp; v.y *= cp; v.z *= cp; v.w *= cp;

    // global float4 index = row*4 + part = blockIdx.x*256 + tid  (coalesced)
    out[(blockIdx.x << 8) + tid] = v;
}

} // namespace

extern "C" void kernel_launch(void* const* d_in, const int* in_sizes, int n_in,
                              void* d_out, int out_size) {
    const float* coords = (const float*)d_in[0];  // (2,1024,3)
    const float* conf   = (const float*)d_in[1];  // (2,1024)
    const float* Wm     = (const float*)d_in[2];  // (22,16)
    const float* bv     = (const float*)d_in[3];  // (16)
    const float* gam    = (const float*)d_in[4];  // (16)
    const float* bet    = (const float*)d_in[5];  // (16)
    float4* out = (float4*)d_out;

    const int total4 = out_size / 4;              // 8,388,608 float4s
    const int blocks = total4 / 256;              // 32,768 blocks
    template_encoder_kernel<<<blocks, 256>>>(coords, conf, Wm, bv, gam, bet, out);
}

// round 4
// speedup vs baseline: 2.1882x; 2.1882x over previous
#include <cuda_runtime.h>
#include <cuda_bf16.h>

// TemplateEncoder: out (B=2, N=1024, N=1024, 16) fp32 = 128 MiB, pure store-BW.
//
// one_hot(bin,22) @ W + b -> LN -> ReLU depends only on the bin index:
// precompute relu(LN(W[k]+b)*gamma+beta) as a 22x16 table once per block.
// out_row(b,i,j) = table[bin(i,j)] * min(conf_i, conf_j).
//
// Layout: 1024 blocks (one wave at occ=8). Block bk -> batch b = bk>>9,
// rows i0 = bk&511 and i0+512 (same batch => shared j staging).
// All 1024 j entries staged once as float4(x,y,z,conf) in smem; table built
// once; then 2x16 barrier-free iterations, 256 coalesced float4 stores each.

namespace {

constexpr int   TD    = 16;
constexpr float BIN_W = 40.0f / 21.0f;
constexpr float INV_W = 21.0f / 40.0f;
constexpr int   TBL_STRIDE = 20;   // floats; 80B rows, 16B aligned, odd bank-group stride

__global__ __launch_bounds__(256, 8) void template_encoder_kernel(
    const float* __restrict__ coords,   // (B, N, 3)
    const float* __restrict__ conf,     // (B, N)
    const float* __restrict__ Wm,       // (22, 16)
    const float* __restrict__ bv,       // (16)
    const float* __restrict__ gam,      // (16)
    const float* __restrict__ bet,      // (16)
    float4* __restrict__ out)
{
    __shared__ float  table[22][TBL_STRIDE];
    __shared__ float4 s_j[1024];        // (x, y, z, conf) per j

    const int tid = threadIdx.x;
    const int b   = blockIdx.x >> 9;
    const int i0  = blockIdx.x & 511;
    const int gb  = b << 10;

    // ---- stage all 1024 j entries for this batch ----
    #pragma unroll
    for (int q = 0; q < 4; ++q) {
        const int j  = (q << 8) + tid;
        const int gj = gb + j;
        float4 v;
        v.x = coords[gj * 3 + 0];
        v.y = coords[gj * 3 + 1];
        v.z = coords[gj * 3 + 2];
        v.w = conf[gj];
        s_j[j] = v;
    }

    // ---- 22x16 bin table: relu(LN(W[k]+b)*gamma+beta) ----
    if (tid < 22) {
        float h[TD];
        float mu = 0.0f;
        #pragma unroll
        for (int d = 0; d < TD; ++d) { h[d] = Wm[tid * TD + d] + bv[d]; mu += h[d]; }
        mu *= (1.0f / TD);
        float var = 0.0f;
        #pragma unroll
        for (int d = 0; d < TD; ++d) { float t = h[d] - mu; var = fmaf(t, t, var); }
        var *= (1.0f / TD);
        const float inv = rsqrtf(var + 1e-5f);
        #pragma unroll
        for (int d = 0; d < TD; ++d)
            table[tid][d] = fmaxf((h[d] - mu) * inv * gam[d] + bet[d], 0.0f);
    }
    __syncthreads();

    const int jl   = tid >> 2;          // local j within a 64-row tile (4 thr/row)
    const int part = tid & 3;           // which float4 of the 16-float feature row

    #pragma unroll
    for (int half = 0; half < 2; ++half) {
        const int   i   = i0 + (half << 9);
        const int   gi  = gb + i;
        const float cix = __ldg(coords + gi * 3 + 0);   // uniform across block
        const float ciy = __ldg(coords + gi * 3 + 1);
        const float ciz = __ldg(coords + gi * 3 + 2);
        const float cfi = __ldg(conf + gi);
        const bool  hi  = cfi > 0.0f;
        const int   base4 = (gb + i) << 12;             // float4 index of row start

        #pragma unroll 2
        for (int k = 0; k < 16; ++k) {
            const float4 cj = s_j[(k << 6) + jl];       // broadcast LDS.128

            const float dx = cix - cj.x;
            const float dy = ciy - cj.y;
            const float dz = ciz - cj.z;
            const float dist =
                sqrtf(fmaf(dx, dx, fmaf(dy, dy, fmaf(dz, dz, 1e-8f))));

            // cnt = #{m in [0,20] : fl(m*BIN_W) < dist}; c = floor guess,
            // exact with two predicated refines (c-1 under/overshoot proven <=1,
            // cnt in {c, c+1, c+2}); bin = min(cnt, 20).
            int c = (int)(dist * INV_W);
            c = c > 21 ? 21 : c;
            const float fc = (float)c;
            int cnt = c;
            if (c     <= 20 &&  fc         * BIN_W < dist) ++cnt;
            if (c + 1 <= 20 && (fc + 1.0f) * BIN_W < dist) ++cnt;
            int bin = cnt > 20 ? 20 : cnt;
            if (!(hi && cj.w > 0.0f)) bin = 21;         // no_template_bin
            const float cp = fminf(cfi, cj.w);

            float4 v = *reinterpret_cast<const float4*>(&table[bin][part << 2]);
            v.x *= cp; v.y *= cp; v.z *= cp; v.w *= cp;

            __stcs(out + base4 + (k << 8) + tid, v);    // coalesced, streaming
        }
    }
}

} // namespace

extern "C" void kernel_launch(void* const* d_in, const int* in_sizes, int n_in,
                              void* d_out, int out_size) {
    const float* coords = (const float*)d_in[0];
    const float* conf   = (const float*)d_in[1];
    const float* Wm     = (const float*)d_in[2];
    const float* bv     = (const float*)d_in[3];
    const float* gam    = (const float*)d_in[4];
    const float* bet    = (const float*)d_in[5];
    template_encoder_kernel<<<1024, 256>>>(coords, conf, Wm, bv, gam, bet,
                                           (float4*)d_out);
}